// round 4
// baseline (speedup 1.0000x reference)
#include <cuda_runtime.h>

#define BB   8
#define CIN  32
#define COUT 32
#define HH   128
#define WW   128
#define SS   1024
#define JJ   (HH*WW)
#define NB   256          // 2 CTAs/SM on 148 SMs, occ_lim>=4 -> all co-resident
#define NT   256

// Scratch (fully overwritten every launch) + monotone barrier counter
// (never reset; each launch adds exactly NB, targets are multiples of NB).
__device__ float g_T[BB*CIN];
__device__ float g_U[BB*CIN];
__device__ float g_V[BB*CIN];
__device__ unsigned int g_bar;   // zero-initialized at module load

__global__ void __launch_bounds__(NT) nystrom_fused(
    const float* __restrict__ v,        // [B, CIN, H, W]
    const float* __restrict__ weight,   // [COUT, CIN, 2]
    const int*   __restrict__ idx32,    // int32 or int64 (detected)
    float*       __restrict__ out)      // [B, COUT, H, W]
{
    const int tid  = threadIdx.x;
    const int lane = tid & 31;
    const int warp = tid >> 5;
    const float step = 2.0f / 127.0f;

    // indices are a permutation (distinct); three zeros at int32 positions
    // 1,3,5 can only be int64 high-halves.
    const bool is64 = (idx32[1] == 0) && (idx32[3] == 0) && (idx32[5] == 0);

    __shared__ float sred[3][8];

    // ---------- Phase 1: gather-reduce T/U/V for ONE (b,i) task --------------
    {
        const int bi = blockIdx.x;               // 0..255 = b*32 + i
        const float* plane = v + (size_t)bi * JJ;

        float t = 0.f, u = 0.f, w = 0.f;
        #pragma unroll
        for (int k = 0; k < 4; ++k) {
            const int s = tid + k * NT;
            const int j = is64 ? idx32[2 * s] : idx32[s];
            const float x = -1.0f + step * (float)(j & (WW - 1));
            const float y = -1.0f + step * (float)(j >> 7);
            const float val = __ldg(plane + j);
            t += val;
            u  = fmaf(x, val, u);
            w  = fmaf(y, val, w);
        }
        #pragma unroll
        for (int off = 16; off > 0; off >>= 1) {
            t += __shfl_down_sync(0xffffffffu, t, off);
            u += __shfl_down_sync(0xffffffffu, u, off);
            w += __shfl_down_sync(0xffffffffu, w, off);
        }
        if (lane == 0) { sred[0][warp] = t; sred[1][warp] = u; sred[2][warp] = w; }
        __syncthreads();
        if (tid == 0) {
            float T = 0.f, U = 0.f, V = 0.f;
            #pragma unroll
            for (int q = 0; q < 8; ++q) { T += sred[0][q]; U += sred[1][q]; V += sred[2][q]; }
            g_T[bi] = T; g_U[bi] = U; g_V[bi] = V;
        }
    }

    // Phase-2 plane ids + weight preload (independent of phase 1 -> hide its
    // cold-miss latency under the barrier wait).
    const int pl = blockIdx.x;                   // b*32 + o
    const int b = pl >> 5;
    const int o = pl & 31;
    const float2 wv = ((const float2*)weight)[o * CIN + lane];

    // ---------- Grid barrier (epoch-based, replay-safe) ----------------------
    if (tid == 0) {
        __threadfence();                                   // release T/U/V
        const unsigned int old = atomicAdd(&g_bar, 1u);
        const unsigned int target = (old / NB + 1u) * NB;  // end of this epoch
        while (atomicAdd(&g_bar, 0u) < target) { __nanosleep(32); }
        __threadfence();                                   // acquire
    }
    __syncthreads();

    // ---------- Phase 2: fill ONE output plane --------------------------------
    {
        // Warp-parallel dot: lane = channel. L2-only loads (skip stale L1).
        const float T = __ldcg(g_T + b * CIN + lane);
        const float U = __ldcg(g_U + b * CIN + lane);
        const float V = __ldcg(g_V + b * CIN + lane);

        float p = T * wv.x;
        float q = T * wv.y;
        float r = fmaf(U, wv.x, V * wv.y);
        #pragma unroll
        for (int off = 16; off > 0; off >>= 1) {
            p += __shfl_xor_sync(0xffffffffu, p, off);
            q += __shfl_xor_sync(0xffffffffu, q, off);
            r += __shfl_xor_sync(0xffffffffu, r, off);
        }
        const float P = p, Q = q, R = r;

        float4* outp = (float4*)(out + (size_t)pl * JJ);
        #pragma unroll
        for (int k = 0; k < 16; ++k) {
            const int q4 = tid + k * NT;           // float4 index in plane [0,4096)
            const int h  = q4 >> 5;
            const int wq = (q4 * 4) & (WW - 1);
            const float y = -1.0f + step * (float)h;
            const float base = fmaf(y, Q, -R);
            const float x0 = -1.0f + step * (float)wq;
            float4 o4;
            o4.x = fmaf(x0,               P, base);
            o4.y = fmaf(x0 +        step, P, base);
            o4.z = fmaf(x0 + 2.0f * step, P, base);
            o4.w = fmaf(x0 + 3.0f * step, P, base);
            outp[q4] = o4;
        }
    }
}

extern "C" void kernel_launch(void* const* d_in, const int* in_sizes, int n_in,
                              void* d_out, int out_size)
{
    const float* v      = (const float*)d_in[0];
    const float* weight = (const float*)d_in[1];
    const int*   idx32  = (const int*)  d_in[2];
    float*       out    = (float*)d_out;

    nystrom_fused<<<NB, NT>>>(v, weight, idx32, out);
}